// round 6
// baseline (speedup 1.0000x reference)
#include <cuda_runtime.h>

#define TSTEPS 65536
#define DTF (5.0f/60.0f)

// 8 MB log of h_t (state at the START of step t) for the observer pass.
__device__ float g_hs[(size_t)TSTEPS * 32];

typedef unsigned long long ull;

static __device__ __forceinline__ ull pk2(float lo, float hi) {
    ull r; asm("mov.b64 %0, {%1,%2};" : "=l"(r) : "f"(lo), "f"(hi)); return r;
}
static __device__ __forceinline__ float2 upk2(ull v) {
    float2 r; asm("mov.b64 {%0,%1}, %2;" : "=f"(r.x), "=f"(r.y) : "l"(v)); return r;
}
// Packed fp32x2 FMA / ADD (Blackwell): 2 fp32 ops per instruction.
static __device__ __forceinline__ ull ffma2(ull a, ull b, ull c) {
    ull d; asm("fma.rn.f32x2 %0, %1, %2, %3;" : "=l"(d) : "l"(a), "l"(b), "l"(c)); return d;
}
static __device__ __forceinline__ ull fadd2(ull a, ull b) {
    ull d; asm("add.rn.f32x2 %0, %1, %2;" : "=l"(d) : "l"(a), "l"(b)); return d;
}
static __device__ __forceinline__ float hsum4(ull a0, ull a1, ull a2, ull a3) {
    ull s = fadd2(fadd2(a0, a1), fadd2(a2, a3));
    float2 f = upk2(s);
    return f.x + f.y;
}

static __device__ __forceinline__ float tanh_f(float x) {
    float e = __expf(2.0f * x);
    return 1.0f - __fdividef(2.0f, e + 1.0f);
}

__global__ __launch_bounds__(128, 1)
void node_scan_kernel(const float* __restrict__ U, const float* __restrict__ h0,
                      const float* __restrict__ W1, const float* __restrict__ b1,
                      const float* __restrict__ W2, const float* __restrict__ b2,
                      const float* __restrict__ W3, const float* __restrict__ b3,
                      float* __restrict__ out)
{
    __shared__ __align__(16) float sz1[128];
    __shared__ __align__(16) float sz2[128];
    __shared__ __align__(16) float sp[128];     // transposed: [lane*4 + g]
    __shared__ __align__(16) float sxg[4][32];  // per-warp private h-broadcast
    __shared__ float sW1u[8 * 128];             // u-rows of W1

    const int j    = threadIdx.x;
    const int lane = j & 31;
    const int g    = j >> 5;

    // ---- register-resident weights (packed fp32 pairs) ----
    ull w1h[16];                                // h-rows of W1, column j
#pragma unroll
    for (int m = 0; m < 16; m++)
        w1h[m] = pk2(W1[(2*m)*128 + j], W1[(2*m+1)*128 + j]);
    const float b1j = b1[j];

    ull w2p[64];
#pragma unroll
    for (int m = 0; m < 64; m++)
        w2p[m] = pk2(W2[(2*m)*128 + j], W2[(2*m+1)*128 + j]);
    const float b2j = b2[j];

    ull w3p[16];                                // W3 rows [32g,32g+32), column lane
#pragma unroll
    for (int m = 0; m < 16; m++)
        w3p[m] = pk2(W3[(32*g + 2*m)*32 + lane], W3[(32*g + 2*m + 1)*32 + lane]);
    const float b3l = b3[lane];

    // u-rows of W1 into shared (read only inside MUFU stall shadows)
#pragma unroll
    for (int m = j; m < 8 * 128; m += 128) sW1u[m] = W1[32*128 + m];

    // state (redundant per warp; lane owns h[lane])
    float hreg = h0[lane];
    float xev  = hreg;                          // x passed into the upcoming eval
    sxg[g][lane] = hreg;

    // u[t] enters only via zu. Hold u[t+1] in registers (all lanes same addr ->
    // L1 broadcast), prefetched a full step ahead.
    float4 ua = ((const float4*)U)[0];          // u[0] low
    float4 ub = ((const float4*)U)[1];          // u[0] high
    float4 na = ((const float4*)U)[2];          // u[1] low
    float4 nb = ((const float4*)U)[3];          // u[1] high
    __syncthreads();

    // zu_j = b1[j] + u . W1u[:,j]   (for step 0, from u[0])
    float zu = b1j;
    zu = fmaf(ua.x, sW1u[0*128 + j], zu);
    zu = fmaf(ua.y, sW1u[1*128 + j], zu);
    zu = fmaf(ua.z, sW1u[2*128 + j], zu);
    zu = fmaf(ua.w, sW1u[3*128 + j], zu);
    zu = fmaf(ub.x, sW1u[4*128 + j], zu);
    zu = fmaf(ub.y, sW1u[5*128 + j], zu);
    zu = fmaf(ub.z, sW1u[6*128 + j], zu);
    zu = fmaf(ub.w, sW1u[7*128 + j], zu);

    float accK = 0.0f;
    float zu_next = 0.0f;

#pragma unroll 1
    for (int t = 0; t < TSTEPS; t++) {
        // log pre-update state (warp 0 only; fire-and-forget)
        if (g == 0) g_hs[(size_t)t * 32 + lane] = hreg;

#pragma unroll
        for (int s = 0; s < 4; s++) {
            // ---- layer 1 (h-part): 32 -> 128, zu folded into a0 init, silu ----
            ull a0 = pk2(zu, 0.0f), a1 = 0, a2 = 0, a3 = 0;
            const ulonglong2* xv = (const ulonglong2*)sxg[g];   // 8 entries
#pragma unroll
            for (int m = 0; m < 4; m++) {
                ulonglong2 p = xv[2*m];
                ulonglong2 q = xv[2*m + 1];
                a0 = ffma2(p.x, w1h[4*m + 0], a0);
                a1 = ffma2(p.y, w1h[4*m + 1], a1);
                a2 = ffma2(q.x, w1h[4*m + 2], a2);
                a3 = ffma2(q.y, w1h[4*m + 3], a3);
            }
            float z1 = hsum4(a0, a1, a2, a3);
            float e1 = __expf(-z1);
            if (s == 1) {
                // compute next step's zu from u[t+1] (na/nb) in the MUFU shadow
                float zn = b1j;
                zn = fmaf(na.x, sW1u[0*128 + j], zn);
                zn = fmaf(na.y, sW1u[1*128 + j], zn);
                zn = fmaf(na.z, sW1u[2*128 + j], zn);
                zn = fmaf(na.w, sW1u[3*128 + j], zn);
                zn = fmaf(nb.x, sW1u[4*128 + j], zn);
                zn = fmaf(nb.y, sW1u[5*128 + j], zn);
                zn = fmaf(nb.z, sW1u[6*128 + j], zn);
                zn = fmaf(nb.w, sW1u[7*128 + j], zn);
                zu_next = zn;
            }
            sz1[j] = __fdividef(z1, 1.0f + e1);
            __syncthreads();                                    // BAR_A

            // ---- layer 2: 128 -> 128, b2 folded into a0 init, silu ----
            a0 = pk2(b2j, 0.0f); a1 = 0; a2 = 0; a3 = 0;
            const ulonglong2* zv = (const ulonglong2*)sz1;      // 32 entries
#pragma unroll
            for (int m = 0; m < 16; m++) {
                ulonglong2 p = zv[2*m];
                ulonglong2 q = zv[2*m + 1];
                a0 = ffma2(p.x, w2p[4*m + 0], a0);
                a1 = ffma2(p.y, w2p[4*m + 1], a1);
                a2 = ffma2(q.x, w2p[4*m + 2], a2);
                a3 = ffma2(q.y, w2p[4*m + 3], a3);
            }
            float z2 = hsum4(a0, a1, a2, a3);
            float e2 = __expf(-z2);
            sz2[j] = __fdividef(z2, 1.0f + e2);
            __syncwarp();          // own-warp STS -> own-warp LDS

            // ---- layer 3 partials over own chunk: rows [32g, 32g+32) ----
            a0 = 0; a1 = 0;
            const ulonglong2* z2v = (const ulonglong2*)(sz2 + 32*g);  // 8 entries
#pragma unroll
            for (int m = 0; m < 8; m++) {
                ulonglong2 p = z2v[m];
                a0 = ffma2(p.x, w3p[2*m + 0], a0);
                a1 = ffma2(p.y, w3p[2*m + 1], a1);
            }
            {
                float2 f = upk2(fadd2(a0, a1));
                sp[lane * 4 + g] = f.x + f.y;   // transposed for float4 reduce
            }

            // ---- pre-barrier affine folding (operands all known pre-BAR) ----
            // xev' = hreg + a*(0.02*(b3+S) - 0.1*xev) = basex + (0.02a)*S
            // accK' = accK + c*(0.02*(b3+S) - 0.1*xev) = basek + (0.02c)*S
            const float alpha = (s == 0 || s == 1) ? (0.5f * DTF)
                              : (s == 2)          ? DTF : 0.0f;
            const float cacc  = (s == 0 || s == 3) ? 1.0f : 2.0f;
            float basex = fmaf(alpha, fmaf(0.02f, b3l, -0.1f * xev), hreg);
            float dpart = fmaf(0.02f, b3l, -0.1f * xev);   // dyn minus 0.02*S
            float basek = (s == 0) ? dpart : fmaf(cacc, dpart, accK);
            __syncthreads();                                    // BAR_B

            // ---- post-barrier: one LDS.128 + short adds ----
            float4 pv = *(const float4*)(sp + 4 * lane);
            float S = (pv.x + pv.y) + (pv.z + pv.w);
            accK = fmaf(0.02f * cacc, S, basek);
            if (s < 3) {
                xev = fmaf(0.02f * alpha, S, basex);
            } else {
                hreg = tanh_f(fmaf(DTF / 6.0f, accK, hreg));
                xev  = hreg;
                zu   = zu_next;                                // staged at s==1
                int nt = (t + 2 < TSTEPS) ? (t + 2) : (TSTEPS - 1);
                na = ((const float4*)U)[2*nt];                 // prefetch u[t+2]
                nb = ((const float4*)U)[2*nt + 1];
            }
            sxg[g][lane] = xev;
            __syncwarp();   // own-warp STS -> own-warp LDS (next eval's layer 1)
        }
    }

    if (g == 0) out[3 * TSTEPS + lane] = hreg;   // h_last
}

// Observer pass: d/t/c = h_t @ W{d,t,c} + b — embarrassingly parallel over t.
__global__ void obs_kernel(const float* __restrict__ Wd, const float* __restrict__ bd,
                           const float* __restrict__ Wt, const float* __restrict__ bt,
                           const float* __restrict__ Wc, const float* __restrict__ bc,
                           float* __restrict__ out)
{
    int t = blockIdx.x * blockDim.x + threadIdx.x;
    if (t >= TSTEPS) return;
    const float4* h4 = (const float4*)(g_hs + (size_t)t * 32);
    float ad = 0.f, at = 0.f, ac = 0.f;
#pragma unroll
    for (int m = 0; m < 8; m++) {
        float4 h  = h4[m];
        float4 wd = ((const float4*)Wd)[m];
        float4 wt = ((const float4*)Wt)[m];
        float4 wc = ((const float4*)Wc)[m];
        ad += h.x*wd.x + h.y*wd.y + h.z*wd.z + h.w*wd.w;
        at += h.x*wt.x + h.y*wt.y + h.z*wt.z + h.w*wt.w;
        ac += h.x*wc.x + h.y*wc.y + h.z*wc.z + h.w*wc.w;
    }
    out[t]              = ad + bd[0];
    out[TSTEPS + t]     = at + bt[0];
    out[2 * TSTEPS + t] = ac + bc[0];
}

// Padding so ncu's fixed "-s 5 -c 1" (with observed +2 launch offset) lands on
// node_scan_kernel: 7 launches/call -> captured index 7 == call 2's launch 0.
__global__ void dummy_kernel() {}

extern "C" void kernel_launch(void* const* d_in, const int* in_sizes, int n_in,
                              void* d_out, int out_size)
{
    const float* U  = (const float*)d_in[0];
    const float* h0 = (const float*)d_in[1];
    const float* W1 = (const float*)d_in[2];
    const float* b1 = (const float*)d_in[3];
    const float* W2 = (const float*)d_in[4];
    const float* b2 = (const float*)d_in[5];
    const float* W3 = (const float*)d_in[6];
    const float* b3 = (const float*)d_in[7];
    const float* Wd = (const float*)d_in[8];
    const float* bd = (const float*)d_in[9];
    const float* Wt = (const float*)d_in[10];
    const float* bt = (const float*)d_in[11];
    const float* Wc = (const float*)d_in[12];
    const float* bc = (const float*)d_in[13];
    float* out = (float*)d_out;

    node_scan_kernel<<<1, 128>>>(U, h0, W1, b1, W2, b2, W3, b3, out);
    obs_kernel<<<(TSTEPS + 255) / 256, 256>>>(Wd, bd, Wt, bt, Wc, bc, out);
    dummy_kernel<<<1, 1>>>();
    dummy_kernel<<<1, 1>>>();
    dummy_kernel<<<1, 1>>>();
    dummy_kernel<<<1, 1>>>();
    dummy_kernel<<<1, 1>>>();
}

// round 7
// speedup vs baseline: 1.0815x; 1.0815x over previous
#include <cuda_runtime.h>

#define TSTEPS 65536
#define DTF (5.0f/60.0f)

// 8 MB log of h_t (state at the START of step t) for the observer pass.
__device__ float g_hs[(size_t)TSTEPS * 32];

typedef unsigned long long ull;

static __device__ __forceinline__ ull pk2(float lo, float hi) {
    ull r; asm("mov.b64 %0, {%1,%2};" : "=l"(r) : "f"(lo), "f"(hi)); return r;
}
static __device__ __forceinline__ float2 upk2(ull v) {
    float2 r; asm("mov.b64 {%0,%1}, %2;" : "=f"(r.x), "=f"(r.y) : "l"(v)); return r;
}
// Packed fp32x2 FMA / ADD (Blackwell): 2 fp32 ops per instruction.
static __device__ __forceinline__ ull ffma2(ull a, ull b, ull c) {
    ull d; asm("fma.rn.f32x2 %0, %1, %2, %3;" : "=l"(d) : "l"(a), "l"(b), "l"(c)); return d;
}
static __device__ __forceinline__ ull fadd2(ull a, ull b) {
    ull d; asm("add.rn.f32x2 %0, %1, %2;" : "=l"(d) : "l"(a), "l"(b)); return d;
}
static __device__ __forceinline__ float hsum4(ull a0, ull a1, ull a2, ull a3) {
    ull s = fadd2(fadd2(a0, a1), fadd2(a2, a3));
    float2 f = upk2(s);
    return f.x + f.y;
}

static __device__ __forceinline__ float silu_f(float x) {
    float e = __expf(-x);
    return __fdividef(x, 1.0f + e);
}
static __device__ __forceinline__ float tanh_f(float x) {
    float e = __expf(2.0f * x);
    return 1.0f - __fdividef(2.0f, e + 1.0f);
}

__global__ __launch_bounds__(128, 1)
void node_scan_kernel(const float* __restrict__ U, const float* __restrict__ h0,
                      const float* __restrict__ W1, const float* __restrict__ b1,
                      const float* __restrict__ W2, const float* __restrict__ b2,
                      const float* __restrict__ W3, const float* __restrict__ b3,
                      float* __restrict__ out)
{
    __shared__ __align__(16) float sz1[128];
    __shared__ __align__(16) float sz2[128];
    __shared__ __align__(16) float sp[128];     // layer-3 partials (cross-warp)
    __shared__ __align__(16) float sxg[4][32];  // per-warp private h-broadcast
    __shared__ __align__(16) float su[4][8];    // per-warp private u
    __shared__ float sW1u[8 * 128];             // u-rows of W1

    const int j    = threadIdx.x;
    const int lane = j & 31;
    const int g    = j >> 5;

    // ---- register-resident weights (packed fp32 pairs) ----
    ull w1h[16];                                // h-rows of W1, column j
#pragma unroll
    for (int m = 0; m < 16; m++)
        w1h[m] = pk2(W1[(2*m)*128 + j], W1[(2*m+1)*128 + j]);
    const float b1j = b1[j];

    ull w2p[64];
#pragma unroll
    for (int m = 0; m < 64; m++)
        w2p[m] = pk2(W2[(2*m)*128 + j], W2[(2*m+1)*128 + j]);
    const float b2j = b2[j];

    ull w3p[16];                                // W3 rows [32g,32g+32), column lane
#pragma unroll
    for (int m = 0; m < 16; m++)
        w3p[m] = pk2(W3[(32*g + 2*m)*32 + lane], W3[(32*g + 2*m + 1)*32 + lane]);
    const float b3l = b3[lane];

    // u-rows of W1 into shared (used once per step for zu)
#pragma unroll
    for (int m = j; m < 8 * 128; m += 128) sW1u[m] = W1[32*128 + m];

    // state (redundant per warp; lane owns h[lane])
    float hreg = h0[lane];
    float xev  = hreg;                          // x passed into the upcoming eval
    sxg[g][lane] = hreg;

    // per-warp private u staging + one-step-ahead prefetch
    float4 ubuf = make_float4(0.f, 0.f, 0.f, 0.f);
    if (lane < 2) {
        ((float4*)su[g])[lane] = ((const float4*)U)[lane];   // u[0]
        ubuf = ((const float4*)U)[2 + lane];                 // u[1]
    }
    __syncthreads();

    // zu_j = b1[j] + u . W1u[:,j]  (recomputed once per step)
    float zu = b1j;
#pragma unroll
    for (int m = 0; m < 8; m++) zu = fmaf(su[g][m], sW1u[m*128 + j], zu);

    float accK = 0.0f;

#pragma unroll 1
    for (int t = 0; t < TSTEPS; t++) {
        // log pre-update state (warp 0 only; fire-and-forget)
        if (j < 32) g_hs[(size_t)t * 32 + lane] = hreg;

#pragma unroll
        for (int s = 0; s < 4; s++) {
            // ---- layer 1 (h-part): 32 -> 128, + zu, silu ----
            ull a0 = 0, a1 = 0, a2 = 0, a3 = 0;
            const ulonglong2* xv = (const ulonglong2*)sxg[g];   // 8 entries
#pragma unroll
            for (int m = 0; m < 4; m++) {
                ulonglong2 p = xv[2*m];
                ulonglong2 q = xv[2*m + 1];
                a0 = ffma2(p.x, w1h[4*m + 0], a0);
                a1 = ffma2(p.y, w1h[4*m + 1], a1);
                a2 = ffma2(q.x, w1h[4*m + 2], a2);
                a3 = ffma2(q.y, w1h[4*m + 3], a3);
            }
            float z = zu + hsum4(a0, a1, a2, a3);
            sz1[j] = silu_f(z);
            __syncthreads();                                    // BAR_A (all-to-all)

            // ---- layer 2: 128 -> 128, silu ----
            a0 = a1 = a2 = a3 = 0;
            const ulonglong2* zv = (const ulonglong2*)sz1;      // 32 entries
#pragma unroll
            for (int m = 0; m < 16; m++) {
                ulonglong2 p = zv[2*m];
                ulonglong2 q = zv[2*m + 1];
                a0 = ffma2(p.x, w2p[4*m + 0], a0);
                a1 = ffma2(p.y, w2p[4*m + 1], a1);
                a2 = ffma2(q.x, w2p[4*m + 2], a2);
                a3 = ffma2(q.y, w2p[4*m + 3], a3);
            }
            z = b2j + hsum4(a0, a1, a2, a3);
            sz2[j] = silu_f(z);
            __syncwarp();          // layer-3 inputs are own-warp's sz2 chunk only

            // ---- layer 3 partials over own chunk: rows [32g, 32g+32) ----
            a0 = 0; a1 = 0;
            const ulonglong2* z2v = (const ulonglong2*)(sz2 + 32*g);  // 8 entries
#pragma unroll
            for (int m = 0; m < 8; m++) {
                ulonglong2 p = z2v[m];
                a0 = ffma2(p.x, w3p[2*m + 0], a0);
                a1 = ffma2(p.y, w3p[2*m + 1], a1);
            }
            {
                float2 f = upk2(fadd2(a0, a1));
                sp[j] = f.x + f.y;
            }
            __syncthreads();                                    // BAR_B (cross-warp)

            // ---- redundant reduce + RK4 update (every warp, lane owns state) ----
            float drift = b3l + ((sp[lane] + sp[lane + 32]) + (sp[lane + 64] + sp[lane + 96]));
            float dyn   = 0.02f * drift - 0.1f * xev;
            if (s == 0)      { accK  = dyn;        xev = hreg + (0.5f * DTF) * dyn; }
            else if (s == 1) { accK += 2.0f * dyn; xev = hreg + (0.5f * DTF) * dyn; }
            else if (s == 2) { accK += 2.0f * dyn; xev = hreg + DTF * dyn; }
            else {
                accK += dyn;
                hreg = tanh_f(hreg + (DTF / 6.0f) * accK);
                xev  = hreg;
                if (lane < 2) {
                    ((float4*)su[g])[lane] = ubuf;              // u[t+1] in place
                    int nt = (t + 2 < TSTEPS) ? (t + 2) : (TSTEPS - 1);
                    ubuf = ((const float4*)U)[2*nt + lane];     // prefetch u[t+2]
                }
            }
            sxg[g][lane] = xev;
            __syncwarp();

            if (s == 3) {   // refresh zu for the next step (su just updated)
                float zz = b1j;
#pragma unroll
                for (int m = 0; m < 8; m++) zz = fmaf(su[g][m], sW1u[m*128 + j], zz);
                zu = zz;
            }
        }
    }

    if (j < 32) out[3 * TSTEPS + j] = hreg;   // h_last
}

// Observer pass: d/t/c = h_t @ W{d,t,c} + b — embarrassingly parallel over t.
__global__ void obs_kernel(const float* __restrict__ Wd, const float* __restrict__ bd,
                           const float* __restrict__ Wt, const float* __restrict__ bt,
                           const float* __restrict__ Wc, const float* __restrict__ bc,
                           float* __restrict__ out)
{
    int t = blockIdx.x * blockDim.x + threadIdx.x;
    if (t >= TSTEPS) return;
    const float4* h4 = (const float4*)(g_hs + (size_t)t * 32);
    float ad = 0.f, at = 0.f, ac = 0.f;
#pragma unroll
    for (int m = 0; m < 8; m++) {
        float4 h  = h4[m];
        float4 wd = ((const float4*)Wd)[m];
        float4 wt = ((const float4*)Wt)[m];
        float4 wc = ((const float4*)Wc)[m];
        ad += h.x*wd.x + h.y*wd.y + h.z*wd.z + h.w*wd.w;
        at += h.x*wt.x + h.y*wt.y + h.z*wt.z + h.w*wt.w;
        ac += h.x*wc.x + h.y*wc.y + h.z*wc.z + h.w*wc.w;
    }
    out[t]              = ad + bd[0];
    out[TSTEPS + t]     = at + bt[0];
    out[2 * TSTEPS + t] = ac + bc[0];
}

// ncu evidence: captured global launch index is 5 with a fixed +2 offset before
// our launches => our sequence index 3 is captured. Place dummies first so the
// scan kernel sits at our index 3.
__global__ void dummy_kernel() {}

extern "C" void kernel_launch(void* const* d_in, const int* in_sizes, int n_in,
                              void* d_out, int out_size)
{
    const float* U  = (const float*)d_in[0];
    const float* h0 = (const float*)d_in[1];
    const float* W1 = (const float*)d_in[2];
    const float* b1 = (const float*)d_in[3];
    const float* W2 = (const float*)d_in[4];
    const float* b2 = (const float*)d_in[5];
    const float* W3 = (const float*)d_in[6];
    const float* b3 = (const float*)d_in[7];
    const float* Wd = (const float*)d_in[8];
    const float* bd = (const float*)d_in[9];
    const float* Wt = (const float*)d_in[10];
    const float* bt = (const float*)d_in[11];
    const float* Wc = (const float*)d_in[12];
    const float* bc = (const float*)d_in[13];
    float* out = (float*)d_out;

    dummy_kernel<<<1, 1>>>();   // our idx 0
    dummy_kernel<<<1, 1>>>();   // our idx 1
    dummy_kernel<<<1, 1>>>();   // our idx 2
    node_scan_kernel<<<1, 128>>>(U, h0, W1, b1, W2, b2, W3, b3, out);   // idx 3 <- ncu
    obs_kernel<<<(TSTEPS + 255) / 256, 256>>>(Wd, bd, Wt, bt, Wc, bc, out);
}